// round 14
// baseline (speedup 1.0000x reference)
#include <cuda_runtime.h>

// FIStateProbabilitiesPaulied: B=256, ND=4, NQ=3 -> D=8, L=64.
// Single fused kernel, grid 256 x 512 (one block per sample).
// Factored Frechet: damp_k = sum_j G~_j dA_k S~_j, G~_j = A^j/j!,
// S~_j = sum_l c_{j,l} u~_l, c_{j,l} = j! l!/(j+l+1)!, u~_l = G~_l[:,0].
// g[p][k] = 2 sum_m Re( i^phs(m,k) * C[p][m][m^mask_k] ),
// C[m][mp][p] = conj(amp_p) * sum_j G~_j[p][m] S~_j[mp].
// R13: G~ chain on warp 0 in registers via shfl (no block barriers in chain),
//      NJ 19->16 (tail ~6e-6 at ||A||~3.2), transposed G storage GT[j][m][p]
//      for conflict-free phase-5 reads, u~ in separate Ur array.
// Output layout: I_k [256*4*64*4*64] then I_b [256*64*64].

#define NJ 16   // j,l = 0..NJ-1

__constant__ float RCPJ[19] = {
    0.f, 1.f, 0.5f, 1.f/3.f, 0.25f, 0.2f, 1.f/6.f, 1.f/7.f, 0.125f,
    1.f/9.f, 0.1f, 1.f/11.f, 1.f/12.f, 1.f/13.f, 1.f/14.f, 1.f/15.f,
    1.f/16.f, 1.f/17.f, 1.f/18.f
};

__global__ __launch_bounds__(512)
void fi_fused_kernel(const float* __restrict__ x,
                     const float* __restrict__ kern,
                     const float* __restrict__ bias,
                     float* __restrict__ out)
{
    const int i = blockIdx.x;
    const int tid = threadIdx.x;   // 512 threads

    __shared__ float pw[64];
    __shared__ float Ar[8][8], Ai[8][8];       // A = -iH
    __shared__ float cjl[NJ][NJ];              // j! l! / (j+l+1)!
    __shared__ float GTr[NJ][8][8], GTi[NJ][8][8];  // GT[j][m][p] = G~_j[p][m]
    __shared__ float Ur[NJ][8], Ui[NJ][8];     // u~_j = G~_j[:,0]
    __shared__ float Sr[NJ][8], Si[NJ][8];     // S~_j
    __shared__ float ampr[8], ampi[8], sIpS[8];
    __shared__ float Cr[8][8][8], Ci[8][8][8]; // [m][mp][p]
    __shared__ __align__(16) float hmat[8][64];  // h[p][k]  (float4-accessed)

    // ---- Phase 1: pw = x@kernel + bias; c_{j,l} table ----
    if (tid < 64) {
        float acc = bias[tid];
        #pragma unroll
        for (int d = 0; d < 4; ++d) acc += x[i*4+d] * kern[d*64+tid];
        pw[tid] = acc;
    } else if (tid >= 128 && tid < 128 + NJ*NJ) {
        int t = tid - 128;
        int j = t >> 4, l = t & 15;          // NJ = 16
        float c = 1.f;
        for (int s = 1; s <= l; ++s) c *= (float)s / (float)(j + s);
        cjl[j][l] = c / (float)(j + l + 1);
    }
    __syncthreads();

    // ---- Phase 2: A = -iH (analytic Pauli build) ----
    if (tid < 64) {
        int r = tid >> 3, c = tid & 7, m = r ^ c;
        float hr = 0.0f, hi = 0.0f;
        #pragma unroll
        for (int sel = 0; sel < 8; ++sel) {
            int k = 0, ph = 0;
            #pragma unroll
            for (int q = 0; q < 3; ++q) {
                int bit = 2 - q;
                int mq = (m >> bit) & 1;
                int sq = (sel >> bit) & 1;
                int d = mq ? (sq ? 2 : 1) : (sq ? 3 : 0);
                k = (k << 2) | d;
                int rb = (r >> bit) & 1;
                if (d == 2) ph += rb ? 1 : 3;        // Y
                else if (d == 3) ph += rb ? 2 : 0;   // Z
            }
            float wv = pw[k];
            switch (ph & 3) {
                case 0: hr += wv; break;
                case 1: hi += wv; break;
                case 2: hr -= wv; break;
                default: hi -= wv; break;
            }
        }
        Ar[r][c] = hi;
        Ai[r][c] = -hr;
    }
    __syncthreads();

    // ---- Phase 3: G~ chain on warp 0, register-resident, shfl matvec ----
    // lane holds G entries (r, c0) and (r, c1), r = lane>>2, c0 = lane&3, c1 = c0+4.
    // G[m][c0] lives in lane (m<<2)|c0 (g0); G[m][c1] in same lane (g1).
    if (tid < 32) {
        const int lane = tid;
        const int r  = lane >> 2;
        const int c0 = lane & 3;
        const int c1 = c0 + 4;

        float ar8[8], ai8[8];
        #pragma unroll
        for (int m = 0; m < 8; ++m) { ar8[m] = Ar[r][m]; ai8[m] = Ai[r][m]; }

        float g0r = (r == c0) ? 1.f : 0.f, g0i = 0.f;
        float g1r = (r == c1) ? 1.f : 0.f, g1i = 0.f;
        GTr[0][c0][r] = g0r; GTi[0][c0][r] = 0.f;
        GTr[0][c1][r] = g1r; GTi[0][c1][r] = 0.f;
        if (c0 == 0) { Ur[0][r] = g0r; Ui[0][r] = 0.f; }

        #pragma unroll 1
        for (int j = 1; j < NJ; ++j) {
            float a0r = 0.f, a0i = 0.f, a1r = 0.f, a1i = 0.f;
            #pragma unroll
            for (int m = 0; m < 8; ++m) {
                const int src = (m << 2) | c0;
                float x0r = __shfl_sync(0xFFFFFFFFu, g0r, src);
                float x0i = __shfl_sync(0xFFFFFFFFu, g0i, src);
                float x1r = __shfl_sync(0xFFFFFFFFu, g1r, src);
                float x1i = __shfl_sync(0xFFFFFFFFu, g1i, src);
                a0r += ar8[m]*x0r - ai8[m]*x0i;
                a0i += ar8[m]*x0i + ai8[m]*x0r;
                a1r += ar8[m]*x1r - ai8[m]*x1i;
                a1i += ar8[m]*x1i + ai8[m]*x1r;
            }
            const float rn = RCPJ[j];
            g0r = a0r*rn; g0i = a0i*rn;
            g1r = a1r*rn; g1i = a1i*rn;
            GTr[j][c0][r] = g0r; GTi[j][c0][r] = g0i;
            GTr[j][c1][r] = g1r; GTi[j][c1][r] = g1i;
            if (c0 == 0) { Ur[j][r] = g0r; Ui[j][r] = g0i; }
        }
    }
    __syncthreads();

    // ---- Phase 4: S~_j[r] (tid<NJ*8) ; amp, 1/sqrt(P) (tid 256..263) ----
    if (tid < NJ*8) {
        int j = tid >> 3, r = tid & 7;
        float sr = 0.f, si = 0.f;
        #pragma unroll
        for (int l = 0; l < NJ; ++l) {
            float c = cjl[j][l];
            sr += c * Ur[l][r];
            si += c * Ui[l][r];
        }
        Sr[j][r] = sr; Si[j][r] = si;
    }
    if (tid >= 256 && tid < 264) {
        int r = tid - 256;
        float ar = 0.f, ai = 0.f;
        #pragma unroll
        for (int j = 0; j < NJ; ++j) { ar += Ur[j][r]; ai += Ui[j][r]; }
        ampr[r] = ar; ampi[r] = ai;
        sIpS[r] = rsqrtf(ar*ar + ai*ai);
    }
    __syncthreads();

    // ---- Phase 5: C[m][mp][p] = conj(amp_p) * sum_j GT[j][m][p] S~_j[mp] ----
    {
        int m  = tid >> 6;
        int mp = (tid >> 3) & 7;
        int p  = tid & 7;
        float dr = 0.f, di = 0.f;
        #pragma unroll
        for (int j = 0; j < NJ; ++j) {
            float gr = GTr[j][m][p], gi = GTi[j][m][p];
            float sr = Sr[j][mp],    si = Si[j][mp];
            dr += gr*sr - gi*si;
            di += gr*si + gi*sr;
        }
        float ar = ampr[p], ai = ampi[p];
        Cr[m][mp][p] = ar*dr + ai*di;    // Re(conj(amp)*D)
        Ci[m][mp][p] = ar*di - ai*dr;    // Im(conj(amp)*D)
    }
    __syncthreads();

    // ---- Phase 6: h[p][k] = 2 * sIp[p] * sum_m Re(i^phs(m,k) C[m][m^mask][p]) ----
    {
        const int k = tid >> 3;
        const int p = tid & 7;
        int d0 = (k>>4)&3, d1 = (k>>2)&3, d2 = k&3;
        int mask = ((d0==1||d0==2)?4:0) | ((d1==1||d1==2)?2:0) | ((d2==1||d2==2)?1:0);
        float g = 0.f;
        #pragma unroll
        for (int m = 0; m < 8; ++m) {
            int ph = 0;
            int b2=(m>>2)&1, b1=(m>>1)&1, b0=m&1;
            if (d0==2) ph += b2?1:3; else if (d0==3) ph += b2?2:0;
            if (d1==2) ph += b1?1:3; else if (d1==3) ph += b1?2:0;
            if (d2==2) ph += b0?1:3; else if (d2==3) ph += b0?2:0;
            int phs = (ph + 3) & 3;              // includes the -i of dA = -i P_k
            float cr = Cr[m][m^mask][p];
            float ci = Ci[m][m^mask][p];
            float term = (phs == 0) ? cr : (phs == 1) ? -ci : (phs == 2) ? -cr : ci;
            g += term;
        }
        hmat[p][k] = 2.0f * g * sIpS[p];
    }

    const float4 xv = ((const float4*)x)[i];
    float xa[4] = {xv.x, xv.y, xv.z, xv.w};
    __syncthreads();

    // ---- Phase 7: fused Gram + streaming store (2 (a,b4) units per thread) ----
    const float4* hm4 = (const float4*)&hmat[0][0];   // [p*16 + b4]
    float4* outk_base = (float4*)out + (size_t)i*16384;
    float4* outb = (float4*)(out + (size_t)256*65536) + (size_t)i*1024;

    #pragma unroll
    for (int u = 0; u < 2; ++u) {
        const int unit = tid + 512*u;
        const int a  = unit >> 4;     // 0..63
        const int b4 = unit & 15;     // float4 index within b

        float4 ib = make_float4(0.f, 0.f, 0.f, 0.f);
        #pragma unroll
        for (int p = 0; p < 8; ++p) {
            float ha = hmat[p][a];
            float4 hb = hm4[p*16 + b4];
            ib.x += ha*hb.x; ib.y += ha*hb.y; ib.z += ha*hb.z; ib.w += ha*hb.w;
        }

        // I_b store
        outb[a*16 + b4] = ib;

        // I_k stores: addr(float4) = j*4096 + a*64 + l*16 + b4
        float4* oj = outk_base + a*64 + b4;
        #pragma unroll
        for (int j = 0; j < 4; ++j) {
            float xj = xa[j];
            #pragma unroll
            for (int l = 0; l < 4; ++l) {
                float sxx = xj * xa[l];
                float4 v;
                v.x = ib.x*sxx; v.y = ib.y*sxx; v.z = ib.z*sxx; v.w = ib.w*sxx;
                oj[j*4096 + l*16] = v;
            }
        }
    }
}

extern "C" void kernel_launch(void* const* d_in, const int* in_sizes, int n_in,
                              void* d_out, int out_size) {
    const float* x = nullptr; const float* k = nullptr; const float* b = nullptr;
    for (int t = 0; t < n_in; ++t) {
        if (in_sizes[t] == 1024 && !x) x = (const float*)d_in[t];
        else if (in_sizes[t] == 256 && !k) k = (const float*)d_in[t];
        else if (in_sizes[t] == 64 && !b) b = (const float*)d_in[t];
    }
    if (!x) x = (const float*)d_in[0];
    if (!k) k = (const float*)d_in[1];
    if (!b) b = (const float*)d_in[2];
    fi_fused_kernel<<<256, 512>>>(x, k, b, (float*)d_out);
}

// round 15
// speedup vs baseline: 1.0695x; 1.0695x over previous
#include <cuda_runtime.h>

// FIStateProbabilitiesPaulied: B=256, ND=4, NQ=3 -> D=8, L=64.
// Two-kernel split (R14):
//   A (grid 256 x 512): factored-Frechet prologue (phases 1-6) -> hmat scratch (512 KB).
//   B (grid 2048 x 128): 8 blocks/sample; per-thread one (a,b4) float4 unit of
//     I_b = h^T h computed in registers, 16 scaled I_k stores + 1 I_b store.
// Factored Frechet: damp_k = sum_j G~_j dA_k S~_j, G~_j = A^j/j!,
// S~_j = sum_l c_{j,l} u~_l, c_{j,l} = j! l!/(j+l+1)!, u~_l = G~_l[:,0].
// g[p][k] = 2 sum_m Re( i^phs(m,k) * C[m][m^mask_k][p] ).
// Output layout: I_k [256*4*64*4*64] then I_b [256*64*64].

#define NJ 16   // j,l = 0..NJ-1

__device__ __align__(16) float g_hmat[256 * 512];   // [i][p(8)][k(64)]

__constant__ float RCPJ[19] = {
    0.f, 1.f, 0.5f, 1.f/3.f, 0.25f, 0.2f, 1.f/6.f, 1.f/7.f, 0.125f,
    1.f/9.f, 0.1f, 1.f/11.f, 1.f/12.f, 1.f/13.f, 1.f/14.f, 1.f/15.f,
    1.f/16.f, 1.f/17.f, 1.f/18.f
};

// ======================= Kernel A: prologue -> hmat =======================
__global__ __launch_bounds__(512)
void prol_kernel(const float* __restrict__ x,
                 const float* __restrict__ kern,
                 const float* __restrict__ bias)
{
    const int i = blockIdx.x;
    const int tid = threadIdx.x;   // 512 threads

    __shared__ float pw[64];
    __shared__ float Ar[8][8], Ai[8][8];       // A = -iH
    __shared__ float cjl[NJ][NJ];              // j! l! / (j+l+1)!
    __shared__ float GTr[NJ][8][8], GTi[NJ][8][8];  // GT[j][m][p] = G~_j[p][m]
    __shared__ float Ur[NJ][8], Ui[NJ][8];     // u~_j = G~_j[:,0]
    __shared__ float Sr[NJ][8], Si[NJ][8];     // S~_j
    __shared__ float ampr[8], ampi[8], sIpS[8];
    __shared__ float Cr[8][8][8], Ci[8][8][8]; // [m][mp][p]
    __shared__ __align__(16) float hmat[8][64];

    // ---- Phase 1: pw = x@kernel + bias; c_{j,l} table ----
    if (tid < 64) {
        float acc = bias[tid];
        #pragma unroll
        for (int d = 0; d < 4; ++d) acc += x[i*4+d] * kern[d*64+tid];
        pw[tid] = acc;
    } else if (tid >= 128 && tid < 128 + NJ*NJ) {
        int t = tid - 128;
        int j = t >> 4, l = t & 15;          // NJ = 16
        float c = 1.f;
        for (int s = 1; s <= l; ++s) c *= (float)s / (float)(j + s);
        cjl[j][l] = c / (float)(j + l + 1);
    }
    __syncthreads();

    // ---- Phase 2: A = -iH (analytic Pauli build) ----
    if (tid < 64) {
        int r = tid >> 3, c = tid & 7, m = r ^ c;
        float hr = 0.0f, hi = 0.0f;
        #pragma unroll
        for (int sel = 0; sel < 8; ++sel) {
            int k = 0, ph = 0;
            #pragma unroll
            for (int q = 0; q < 3; ++q) {
                int bit = 2 - q;
                int mq = (m >> bit) & 1;
                int sq = (sel >> bit) & 1;
                int d = mq ? (sq ? 2 : 1) : (sq ? 3 : 0);
                k = (k << 2) | d;
                int rb = (r >> bit) & 1;
                if (d == 2) ph += rb ? 1 : 3;        // Y
                else if (d == 3) ph += rb ? 2 : 0;   // Z
            }
            float wv = pw[k];
            switch (ph & 3) {
                case 0: hr += wv; break;
                case 1: hi += wv; break;
                case 2: hr -= wv; break;
                default: hi -= wv; break;
            }
        }
        Ar[r][c] = hi;
        Ai[r][c] = -hr;
    }
    __syncthreads();

    // ---- Phase 3: G~ chain on warp 0, register-resident, shfl matvec ----
    if (tid < 32) {
        const int lane = tid;
        const int r  = lane >> 2;
        const int c0 = lane & 3;
        const int c1 = c0 + 4;

        float ar8[8], ai8[8];
        #pragma unroll
        for (int m = 0; m < 8; ++m) { ar8[m] = Ar[r][m]; ai8[m] = Ai[r][m]; }

        float g0r = (r == c0) ? 1.f : 0.f, g0i = 0.f;
        float g1r = (r == c1) ? 1.f : 0.f, g1i = 0.f;
        GTr[0][c0][r] = g0r; GTi[0][c0][r] = 0.f;
        GTr[0][c1][r] = g1r; GTi[0][c1][r] = 0.f;
        if (c0 == 0) { Ur[0][r] = g0r; Ui[0][r] = 0.f; }

        #pragma unroll 1
        for (int j = 1; j < NJ; ++j) {
            float a0r = 0.f, a0i = 0.f, a1r = 0.f, a1i = 0.f;
            #pragma unroll
            for (int m = 0; m < 8; ++m) {
                const int src = (m << 2) | c0;
                float x0r = __shfl_sync(0xFFFFFFFFu, g0r, src);
                float x0i = __shfl_sync(0xFFFFFFFFu, g0i, src);
                float x1r = __shfl_sync(0xFFFFFFFFu, g1r, src);
                float x1i = __shfl_sync(0xFFFFFFFFu, g1i, src);
                a0r += ar8[m]*x0r - ai8[m]*x0i;
                a0i += ar8[m]*x0i + ai8[m]*x0r;
                a1r += ar8[m]*x1r - ai8[m]*x1i;
                a1i += ar8[m]*x1i + ai8[m]*x1r;
            }
            const float rn = RCPJ[j];
            g0r = a0r*rn; g0i = a0i*rn;
            g1r = a1r*rn; g1i = a1i*rn;
            GTr[j][c0][r] = g0r; GTi[j][c0][r] = g0i;
            GTr[j][c1][r] = g1r; GTi[j][c1][r] = g1i;
            if (c0 == 0) { Ur[j][r] = g0r; Ui[j][r] = g0i; }
        }
    }
    __syncthreads();

    // ---- Phase 4: S~_j[r] ; amp, 1/sqrt(P) ----
    if (tid < NJ*8) {
        int j = tid >> 3, r = tid & 7;
        float sr = 0.f, si = 0.f;
        #pragma unroll
        for (int l = 0; l < NJ; ++l) {
            float c = cjl[j][l];
            sr += c * Ur[l][r];
            si += c * Ui[l][r];
        }
        Sr[j][r] = sr; Si[j][r] = si;
    }
    if (tid >= 256 && tid < 264) {
        int r = tid - 256;
        float ar = 0.f, ai = 0.f;
        #pragma unroll
        for (int j = 0; j < NJ; ++j) { ar += Ur[j][r]; ai += Ui[j][r]; }
        ampr[r] = ar; ampi[r] = ai;
        sIpS[r] = rsqrtf(ar*ar + ai*ai);
    }
    __syncthreads();

    // ---- Phase 5: C[m][mp][p] = conj(amp_p) * sum_j GT[j][m][p] S~_j[mp] ----
    {
        int m  = tid >> 6;
        int mp = (tid >> 3) & 7;
        int p  = tid & 7;
        float dr = 0.f, di = 0.f;
        #pragma unroll
        for (int j = 0; j < NJ; ++j) {
            float gr = GTr[j][m][p], gi = GTi[j][m][p];
            float sr = Sr[j][mp],    si = Si[j][mp];
            dr += gr*sr - gi*si;
            di += gr*si + gi*sr;
        }
        float ar = ampr[p], ai = ampi[p];
        Cr[m][mp][p] = ar*dr + ai*di;    // Re(conj(amp)*D)
        Ci[m][mp][p] = ar*di - ai*dr;    // Im(conj(amp)*D)
    }
    __syncthreads();

    // ---- Phase 6: h[p][k] = 2 sIp[p] sum_m Re(i^phs(m,k) C[m][m^mask][p]) ----
    {
        const int k = tid >> 3;
        const int p = tid & 7;
        int d0 = (k>>4)&3, d1 = (k>>2)&3, d2 = k&3;
        int mask = ((d0==1||d0==2)?4:0) | ((d1==1||d1==2)?2:0) | ((d2==1||d2==2)?1:0);
        float g = 0.f;
        #pragma unroll
        for (int m = 0; m < 8; ++m) {
            int ph = 0;
            int b2=(m>>2)&1, b1=(m>>1)&1, b0=m&1;
            if (d0==2) ph += b2?1:3; else if (d0==3) ph += b2?2:0;
            if (d1==2) ph += b1?1:3; else if (d1==3) ph += b1?2:0;
            if (d2==2) ph += b0?1:3; else if (d2==3) ph += b0?2:0;
            int phs = (ph + 3) & 3;              // includes the -i of dA = -i P_k
            float cr = Cr[m][m^mask][p];
            float ci = Ci[m][m^mask][p];
            float term = (phs == 0) ? cr : (phs == 1) ? -ci : (phs == 2) ? -cr : ci;
            g += term;
        }
        hmat[p][k] = 2.0f * g * sIpS[p];
    }
    __syncthreads();

    // ---- coalesced dump to scratch ----
    if (tid < 128) {
        float4* dst = (float4*)(g_hmat + (size_t)i*512);
        dst[tid] = ((const float4*)&hmat[0][0])[tid];
    }
}

// ======================= Kernel B: fused Gram + streaming store =======================
// grid = 2048 (8 blocks/sample), block = 128; thread owns one (a,b4) float4 unit.
__global__ __launch_bounds__(128)
void store_kernel(const float* __restrict__ x,
                  float* __restrict__ out)
{
    const int i = blockIdx.x >> 3;
    const int q = blockIdx.x & 7;
    const int tid = threadIdx.x;

    __shared__ __align__(16) float hmat[8][64];

    ((float4*)&hmat[0][0])[tid] = ((const float4*)(g_hmat + (size_t)i*512))[tid];
    const float4 xv = ((const float4*)x)[i];
    float xa[4] = {xv.x, xv.y, xv.z, xv.w};
    __syncthreads();

    const int unit = (q << 7) | tid;    // 0..1023
    const int a  = unit >> 4;           // 0..63
    const int b4 = unit & 15;           // float4 index within b

    const float4* hm4 = (const float4*)&hmat[0][0];   // [p*16 + b4]
    float4 ib = make_float4(0.f, 0.f, 0.f, 0.f);
    #pragma unroll
    for (int p = 0; p < 8; ++p) {
        float ha = hmat[p][a];
        float4 hb = hm4[p*16 + b4];
        ib.x += ha*hb.x; ib.y += ha*hb.y; ib.z += ha*hb.z; ib.w += ha*hb.w;
    }

    // I_b store (unit-unique)
    {
        float4* outb = (float4*)(out + (size_t)256*65536) + (size_t)i*1024;
        outb[a*16 + b4] = ib;
    }

    // I_k stores: addr(float4) = j*4096 + a*64 + l*16 + b4
    {
        float4* oj = (float4*)out + (size_t)i*16384 + a*64 + b4;
        #pragma unroll
        for (int j = 0; j < 4; ++j) {
            float xj = xa[j];
            #pragma unroll
            for (int l = 0; l < 4; ++l) {
                float sxx = xj * xa[l];
                float4 v;
                v.x = ib.x*sxx; v.y = ib.y*sxx; v.z = ib.z*sxx; v.w = ib.w*sxx;
                oj[j*4096 + l*16] = v;
            }
        }
    }
}

extern "C" void kernel_launch(void* const* d_in, const int* in_sizes, int n_in,
                              void* d_out, int out_size) {
    const float* x = nullptr; const float* k = nullptr; const float* b = nullptr;
    for (int t = 0; t < n_in; ++t) {
        if (in_sizes[t] == 1024 && !x) x = (const float*)d_in[t];
        else if (in_sizes[t] == 256 && !k) k = (const float*)d_in[t];
        else if (in_sizes[t] == 64 && !b) b = (const float*)d_in[t];
    }
    if (!x) x = (const float*)d_in[0];
    if (!k) k = (const float*)d_in[1];
    if (!b) b = (const float*)d_in[2];
    prol_kernel<<<256, 512>>>(x, k, b);
    store_kernel<<<2048, 128>>>(x, (float*)d_out);
}